// round 11
// baseline (speedup 1.0000x reference)
#include <cuda_runtime.h>
#include <cuda_fp16.h>
#include <math.h>

// Problem constants
#define Bn 16
#define Nn 256
#define Fn 64
#define Hn 128

// Table constants (nearest-neighbor lookup)
#define Tn 512
#define D_MAX 1.7320509f
#define TROW 128  // bytes per table row: 64 features x half

// Table row layout (interleaved for conflict-free LDS.128):
//   chunk c (16 bytes), c = 0..7:
//     halves [0..3] = g[k][4c .. 4c+3]
//     halves [4..7] = g[k][32+4c .. 32+4c+3]
__device__ uint4 g_table_raw[(Tn * TROW) / 16];

__device__ __forceinline__ float softplus_acc(float x) {
    // matches jax.nn.softplus = logaddexp(x, 0), stable for all x
    return fmaxf(x, 0.0f) + log1pf(expf(-fabsf(x)));
}

__device__ __forceinline__ __half2 u2h2(unsigned v) {
    return *reinterpret_cast<__half2*>(&v);
}

// ---------------------------------------------------------------------------
// Kernel 1: g[k][f] = softplus( sum_h softplus(d_k*w1+b1)*W2[h,f] + b2[f] )
// stored as half in the interleaved chunk layout. grid = Tn, block = Hn.
// ---------------------------------------------------------------------------
__global__ void build_table_kernel(const float* __restrict__ w1,
                                   const float* __restrict__ b1,
                                   const float* __restrict__ W2,
                                   const float* __restrict__ b2) {
    __shared__ float u[Hn];
    const int k = blockIdx.x;
    const int h = threadIdx.x;  // 0..127
    const float d = (float)k * (D_MAX / (float)(Tn - 1));
    u[h] = softplus_acc(fmaf(d, w1[h], b1[h]));
    __syncthreads();
    if (h < Fn) {
        float acc = b2[h];
#pragma unroll
        for (int hh = 0; hh < Hn; ++hh)
            acc = fmaf(u[hh], W2[hh * Fn + h], acc);
        const __half g = __float2half(softplus_acc(acc));
        __half* tabh = (__half*)g_table_raw;
        const int c = (h < 32) ? (h >> 2) : ((h - 32) >> 2);
        const int slot = (h < 32) ? (h & 3) : (4 + (h & 3));
        tabh[k * 64 + c * 8 + slot] = g;
    }
}

// ---------------------------------------------------------------------------
// Kernel 2: main reduction.
// grid = 128 CTAs (32 output rows each), block = 512 threads (16 warps).
// Thread (fq = tid&7, rq = (tid>>3)&3, rg = (tid>>5)&1, jo = tid>>6) owns
// features {4fq..4fq+3} u {32+4fq..+3} of the FOUR rows rg*16+rq*4+[0,4),
// for j-octile jo (32 j). One fv load feeds 4 rows (fv amortized 16x per
// warp); dsm packs 4 row-offsets per (row-quad, j) into a uint2.
// Per (warp, j): table 16 wf + fv 4 wf + dsm 2 wf = 22 wf per 16 rows.
// ---------------------------------------------------------------------------
__global__ void __launch_bounds__(512, 1)
mp_main_kernel(const float* __restrict__ r, const float* __restrict__ f,
               float* __restrict__ out) {
    extern __shared__ float sm[];
    char* tab = (char*)sm;                            // 512*128B = 64 KB
    char* fh = (char*)sm + 65536;                     // [j][64] half = 32 KB
    unsigned* dsm3 = (unsigned*)((char*)sm + 98304);  // [8][256] uint2 = 16 KB
    float* rstage = (float*)((char*)sm + 114688);     // 768 f32 = 3 KB

    const int tid = threadIdx.x;
    const int cta = blockIdx.x;             // 0..127
    const int b = cta >> 3;                 // 8 CTAs per batch element
    const int i0 = (cta & 7) * 32;          // first local row of this tile

    // A) kick off table copy immediately
#pragma unroll
    for (int e = tid, it = 0; it < (Tn * TROW) / 16 / 512; ++it, e += 512)
        ((uint4*)tab)[e] = g_table_raw[e];

    // B) stage r[b] (256x3 floats)
    for (int e = tid; e < Nn * 3; e += 512)
        rstage[e] = r[b * Nn * 3 + e];
    __syncthreads();

    // C) packed offsets per row-quad: dsm3[rgq*256+j] (uint2) holds the 4
    //    table byte-offsets of rows rgq*4..rgq*4+3 (u16 each);
    //    plus f[b] staged as half in the table-matching interleaved layout.
    const float scale = (float)(Tn - 1) / D_MAX;
    for (int e = tid; e < 8 * Nn; e += 512) {
        const int j = e & 255;
        const int rgq = e >> 8;            // 0..7: row-quad index
        const int ig = i0 + rgq * 4;
        const float jx = rstage[j * 3 + 0];
        const float jy = rstage[j * 3 + 1];
        const float jz = rstage[j * 3 + 2];
        unsigned o[4];
#pragma unroll
        for (int rr = 0; rr < 4; ++rr) {
            const float dx = rstage[(ig + rr) * 3 + 0] - jx;
            const float dy = rstage[(ig + rr) * 3 + 1] - jy;
            const float dz = rstage[(ig + rr) * 3 + 2] - jz;
            const float s = fmaf(dx, dx, fmaf(dy, dy, dz * dz));
            float d;
            asm("sqrt.approx.f32 %0, %1;" : "=f"(d) : "f"(s));  // sqrt(0)=0
            int k = __float2int_rn(d * scale);
            k = min(k, Tn - 1);
            o[rr] = (unsigned)k << 7;  // k * TROW, fits u16
        }
        ((uint2*)dsm3)[e] = make_uint2(o[0] | (o[1] << 16), o[2] | (o[3] << 16));
    }
    for (int e = tid; e < Nn * (Fn / 4); e += 512) {
        const int j = e >> 4;
        const int q = e & 15;
        const float4 v = ((const float4*)(f + b * Nn * Fn))[e];
        const __half2 h01 = __floats2half2_rn(v.x, v.y);
        const __half2 h23 = __floats2half2_rn(v.z, v.w);
        const int c = (q < 8) ? q : (q - 8);
        const int slot = (q < 8) ? 0 : 4;
        __half* dst = (__half*)fh + j * 64 + c * 8 + slot;
        *(__half2*)(dst) = h01;
        *(__half2*)(dst + 2) = h23;
    }
    __syncthreads();

    // D) main loop: 32 j per thread, 4 rows x 8 features, flush every 8 j
    const int fq = tid & 7;
    const int rq = (tid >> 3) & 3;
    const int rg = (tid >> 5) & 1;
    const int jo = tid >> 6;                 // 0..7
    const int rgq = rg * 4 + rq;
    const char* tabp = tab + fq * 16;
    const int jbase = jo << 5;               // 32 j per octile
    const uint4* dpq = (const uint4*)(dsm3 + (rgq * 256 + jbase) * 2);
    const char* fvp = fh + fq * 16 + jbase * 128;

    // acc[row][half]: row 0..3, half 0 = feats 4fq.., half 1 = feats 32+4fq..
    float4 acc[4][2];
#pragma unroll
    for (int rr = 0; rr < 4; ++rr)
#pragma unroll
        for (int hh = 0; hh < 2; ++hh)
            acc[rr][hh] = make_float4(0.f, 0.f, 0.f, 0.f);

#pragma unroll
    for (int q8 = 0; q8 < 4; ++q8) {
        const char* fv8 = fvp + q8 * 1024;
        uint4 dq[4];
#pragma unroll
        for (int t = 0; t < 4; ++t)
            dq[t] = dpq[q8 * 4 + t];

        const __half2 hz = __floats2half2_rn(0.f, 0.f);
        __half2 hacc[4][4];
#pragma unroll
        for (int rr = 0; rr < 4; ++rr)
#pragma unroll
            for (int cc = 0; cc < 4; ++cc)
                hacc[rr][cc] = hz;

#pragma unroll
        for (int jj = 0; jj < 8; ++jj) {
            const unsigned w01 = (jj & 1) ? dq[jj >> 1].z : dq[jj >> 1].x;
            const unsigned w23 = (jj & 1) ? dq[jj >> 1].w : dq[jj >> 1].y;
            const uint4 fvv = *(const uint4*)(fv8 + jj * 128);
            const uint4 v0 = *(const uint4*)(tabp + (w01 & 0xFFFFu));
            const uint4 v1 = *(const uint4*)(tabp + (w01 >> 16));
            const uint4 v2 = *(const uint4*)(tabp + (w23 & 0xFFFFu));
            const uint4 v3 = *(const uint4*)(tabp + (w23 >> 16));

            hacc[0][0] = __hfma2(u2h2(v0.x), u2h2(fvv.x), hacc[0][0]);
            hacc[0][1] = __hfma2(u2h2(v0.y), u2h2(fvv.y), hacc[0][1]);
            hacc[0][2] = __hfma2(u2h2(v0.z), u2h2(fvv.z), hacc[0][2]);
            hacc[0][3] = __hfma2(u2h2(v0.w), u2h2(fvv.w), hacc[0][3]);
            hacc[1][0] = __hfma2(u2h2(v1.x), u2h2(fvv.x), hacc[1][0]);
            hacc[1][1] = __hfma2(u2h2(v1.y), u2h2(fvv.y), hacc[1][1]);
            hacc[1][2] = __hfma2(u2h2(v1.z), u2h2(fvv.z), hacc[1][2]);
            hacc[1][3] = __hfma2(u2h2(v1.w), u2h2(fvv.w), hacc[1][3]);
            hacc[2][0] = __hfma2(u2h2(v2.x), u2h2(fvv.x), hacc[2][0]);
            hacc[2][1] = __hfma2(u2h2(v2.y), u2h2(fvv.y), hacc[2][1]);
            hacc[2][2] = __hfma2(u2h2(v2.z), u2h2(fvv.z), hacc[2][2]);
            hacc[2][3] = __hfma2(u2h2(v2.w), u2h2(fvv.w), hacc[2][3]);
            hacc[3][0] = __hfma2(u2h2(v3.x), u2h2(fvv.x), hacc[3][0]);
            hacc[3][1] = __hfma2(u2h2(v3.y), u2h2(fvv.y), hacc[3][1]);
            hacc[3][2] = __hfma2(u2h2(v3.z), u2h2(fvv.z), hacc[3][2]);
            hacc[3][3] = __hfma2(u2h2(v3.w), u2h2(fvv.w), hacc[3][3]);
        }

#pragma unroll
        for (int rr = 0; rr < 4; ++rr) {
            float2 q0 = __half22float2(hacc[rr][0]);
            float2 q1 = __half22float2(hacc[rr][1]);
            acc[rr][0].x += q0.x; acc[rr][0].y += q0.y;
            acc[rr][0].z += q1.x; acc[rr][0].w += q1.y;
            q0 = __half22float2(hacc[rr][2]);
            q1 = __half22float2(hacc[rr][3]);
            acc[rr][1].x += q0.x; acc[rr][1].y += q0.y;
            acc[rr][1].z += q1.x; acc[rr][1].w += q1.y;
        }
    }

    // E) 3-round log-tree reduction over the 8 jo octiles.
    //    Scratch layout [chunk i][slot] (float4) -> conflict-free STS/LDS.
    float4* red4 = (float4*)fh;
    const int low6 = tid & 63;  // = rg*32 + rq*8 + fq, unique per (rgq, fq)
    __syncthreads();  // all fv reads done before overwrite

#pragma unroll
    for (int round = 0; round < 3; ++round) {
        const int half = 4 >> round;  // 4, 2, 1
        if (jo >= half && jo < 2 * half) {
            const int slot = (jo - half) * 64 + low6;
#pragma unroll
            for (int rr = 0; rr < 4; ++rr) {
                red4[(rr * 2 + 0) * 256 + slot] = acc[rr][0];
                red4[(rr * 2 + 1) * 256 + slot] = acc[rr][1];
            }
        }
        __syncthreads();
        if (jo < half) {
            const int slot = jo * 64 + low6;
#pragma unroll
            for (int rr = 0; rr < 4; ++rr) {
#pragma unroll
                for (int hh = 0; hh < 2; ++hh) {
                    const float4 p = red4[(rr * 2 + hh) * 256 + slot];
                    acc[rr][hh].x += p.x; acc[rr][hh].y += p.y;
                    acc[rr][hh].z += p.z; acc[rr][hh].w += p.w;
                }
            }
        }
        __syncthreads();
    }

    if (jo == 0) {
        const int row0 = cta * 32 + rgq * 4;
#pragma unroll
        for (int rr = 0; rr < 4; ++rr) {
            float4 o;
            o.x = softplus_acc(acc[rr][0].x); o.y = softplus_acc(acc[rr][0].y);
            o.z = softplus_acc(acc[rr][0].z); o.w = softplus_acc(acc[rr][0].w);
            *(float4*)(out + (row0 + rr) * Fn + fq * 4) = o;
            o.x = softplus_acc(acc[rr][1].x); o.y = softplus_acc(acc[rr][1].y);
            o.z = softplus_acc(acc[rr][1].z); o.w = softplus_acc(acc[rr][1].w);
            *(float4*)(out + (row0 + rr) * Fn + 32 + fq * 4) = o;
        }
    }
}

// ---------------------------------------------------------------------------
extern "C" void kernel_launch(void* const* d_in, const int* in_sizes, int n_in,
                              void* d_out, int out_size) {
    const float* r_batch = (const float*)d_in[0];  // [16,256,3]
    const float* f_batch = (const float*)d_in[1];  // [16,256,64]
    const float* w1 = (const float*)d_in[2];       // [128]
    const float* b1 = (const float*)d_in[3];       // [128]
    const float* W2 = (const float*)d_in[4];       // [128,64]
    const float* b2 = (const float*)d_in[5];       // [64]
    float* out = (float*)d_out;                    // [16,256,64]

    build_table_kernel<<<Tn, Hn>>>(w1, b1, W2, b2);

    const int smem_bytes = 114688 + 3072;  // ~115 KB
    static bool attr_set = false;
    if (!attr_set) {
        cudaFuncSetAttribute(mp_main_kernel,
                             cudaFuncAttributeMaxDynamicSharedMemorySize,
                             smem_bytes);
        attr_set = true;
    }
    mp_main_kernel<<<(Bn * Nn) / 32, 512, smem_bytes>>>(r_batch, f_batch, out);
}

// round 12
// speedup vs baseline: 1.0015x; 1.0015x over previous
#include <cuda_runtime.h>
#include <cuda_fp16.h>
#include <math.h>

// Problem constants
#define Bn 16
#define Nn 256
#define Fn 64
#define Hn 128

// Table constants (nearest-neighbor lookup)
#define Tn 512
#define D_MAX 1.7320509f
#define TROW 128  // bytes per table row: 64 features x half

// Table row layout (interleaved for conflict-free LDS.128):
//   chunk c (16 bytes), c = 0..7:
//     halves [0..3] = g[k][4c .. 4c+3]
//     halves [4..7] = g[k][32+4c .. 32+4c+3]
__device__ uint4 g_table_raw[(Tn * TROW) / 16];

__device__ __forceinline__ float softplus_acc(float x) {
    // matches jax.nn.softplus = logaddexp(x, 0), stable for all x
    return fmaxf(x, 0.0f) + log1pf(expf(-fabsf(x)));
}

__device__ __forceinline__ __half2 u2h2(unsigned v) {
    return *reinterpret_cast<__half2*>(&v);
}

// ---------------------------------------------------------------------------
// Kernel 1: g[k][f] = softplus( sum_h softplus(d_k*w1+b1)*W2[h,f] + b2[f] )
// stored as half in the interleaved chunk layout. grid = Tn, block = Hn.
// ---------------------------------------------------------------------------
__global__ void build_table_kernel(const float* __restrict__ w1,
                                   const float* __restrict__ b1,
                                   const float* __restrict__ W2,
                                   const float* __restrict__ b2) {
    __shared__ float u[Hn];
    const int k = blockIdx.x;
    const int h = threadIdx.x;  // 0..127
    const float d = (float)k * (D_MAX / (float)(Tn - 1));
    u[h] = softplus_acc(fmaf(d, w1[h], b1[h]));
    __syncthreads();
    if (h < Fn) {
        float acc = b2[h];
#pragma unroll
        for (int hh = 0; hh < Hn; ++hh)
            acc = fmaf(u[hh], W2[hh * Fn + h], acc);
        const __half g = __float2half(softplus_acc(acc));
        __half* tabh = (__half*)g_table_raw;
        const int c = (h < 32) ? (h >> 2) : ((h - 32) >> 2);
        const int slot = (h < 32) ? (h & 3) : (4 + (h & 3));
        tabh[k * 64 + c * 8 + slot] = g;
    }
}

// ---------------------------------------------------------------------------
// Kernel 2: main reduction.
// grid = 256 CTAs (16 output rows each), block = 256 threads (8 warps),
// smem ~107KB -> TWO co-resident CTAs per SM. The second CTA's main loop
// fills the first CTA's staging/barrier/latency stalls (and vice versa).
// Thread (fq = tid&7, rq = (tid>>3)&3, jo = tid>>5) owns features
// {4fq..4fq+3} u {32+4fq..+3} of the 4 rows rq*4+[0,4), j-octile jo (32 j).
// ---------------------------------------------------------------------------
__global__ void __launch_bounds__(256, 2)
mp_main_kernel(const float* __restrict__ r, const float* __restrict__ f,
               float* __restrict__ out) {
    extern __shared__ float sm[];
    char* tab = (char*)sm;                            // 512*128B = 64 KB
    char* fh = (char*)sm + 65536;                     // [j][64] half = 32 KB
    unsigned* dsm3 = (unsigned*)((char*)sm + 98304);  // [4][256] uint2 = 8 KB
    float* rstage = (float*)((char*)sm + 106496);     // 768 f32 = 3 KB

    const int tid = threadIdx.x;
    const int cta = blockIdx.x;             // 0..255
    const int b = cta >> 4;                 // 16 CTAs per batch element
    const int i0 = (cta & 15) * 16;         // first local row of this tile

    // A) kick off table copy immediately
#pragma unroll
    for (int e = tid, it = 0; it < (Tn * TROW) / 16 / 256; ++it, e += 256)
        ((uint4*)tab)[e] = g_table_raw[e];

    // B) stage r[b] (256x3 floats)
    for (int e = tid; e < Nn * 3; e += 256)
        rstage[e] = r[b * Nn * 3 + e];
    __syncthreads();

    // C) packed offsets per row-quad: dsm3[rq*256+j] (uint2) holds the 4
    //    table byte-offsets of rows rq*4..rq*4+3 (u16 each);
    //    plus f[b] staged as half in the table-matching interleaved layout.
    const float scale = (float)(Tn - 1) / D_MAX;
    for (int e = tid; e < 4 * Nn; e += 256) {
        const int j = e & 255;
        const int rq = e >> 8;             // 0..3: row-quad index
        const int ig = i0 + rq * 4;
        const float jx = rstage[j * 3 + 0];
        const float jy = rstage[j * 3 + 1];
        const float jz = rstage[j * 3 + 2];
        unsigned o[4];
#pragma unroll
        for (int rr = 0; rr < 4; ++rr) {
            const float dx = rstage[(ig + rr) * 3 + 0] - jx;
            const float dy = rstage[(ig + rr) * 3 + 1] - jy;
            const float dz = rstage[(ig + rr) * 3 + 2] - jz;
            const float s = fmaf(dx, dx, fmaf(dy, dy, dz * dz));
            float d;
            asm("sqrt.approx.f32 %0, %1;" : "=f"(d) : "f"(s));  // sqrt(0)=0
            int k = __float2int_rn(d * scale);
            k = min(k, Tn - 1);
            o[rr] = (unsigned)k << 7;  // k * TROW, fits u16
        }
        ((uint2*)dsm3)[e] = make_uint2(o[0] | (o[1] << 16), o[2] | (o[3] << 16));
    }
    for (int e = tid; e < Nn * (Fn / 4); e += 256) {
        const int j = e >> 4;
        const int q = e & 15;
        const float4 v = ((const float4*)(f + b * Nn * Fn))[e];
        const __half2 h01 = __floats2half2_rn(v.x, v.y);
        const __half2 h23 = __floats2half2_rn(v.z, v.w);
        const int c = (q < 8) ? q : (q - 8);
        const int slot = (q < 8) ? 0 : 4;
        __half* dst = (__half*)fh + j * 64 + c * 8 + slot;
        *(__half2*)(dst) = h01;
        *(__half2*)(dst + 2) = h23;
    }
    __syncthreads();

    // D) main loop: 32 j per thread, 4 rows x 8 features, flush every 8 j
    const int fq = tid & 7;
    const int rq = (tid >> 3) & 3;
    const int jo = tid >> 5;                 // 0..7
    const char* tabp = tab + fq * 16;
    const int jbase = jo << 5;               // 32 j per octile
    const uint4* dpq = (const uint4*)(dsm3 + (rq * 256 + jbase) * 2);
    const char* fvp = fh + fq * 16 + jbase * 128;

    // acc[row][half]: row 0..3, half 0 = feats 4fq.., half 1 = feats 32+4fq..
    float4 acc[4][2];
#pragma unroll
    for (int rr = 0; rr < 4; ++rr)
#pragma unroll
        for (int hh = 0; hh < 2; ++hh)
            acc[rr][hh] = make_float4(0.f, 0.f, 0.f, 0.f);

#pragma unroll
    for (int q8 = 0; q8 < 4; ++q8) {
        const char* fv8 = fvp + q8 * 1024;
        uint4 dq[4];
#pragma unroll
        for (int t = 0; t < 4; ++t)
            dq[t] = dpq[q8 * 4 + t];

        const __half2 hz = __floats2half2_rn(0.f, 0.f);
        __half2 hacc[4][4];
#pragma unroll
        for (int rr = 0; rr < 4; ++rr)
#pragma unroll
            for (int cc = 0; cc < 4; ++cc)
                hacc[rr][cc] = hz;

#pragma unroll
        for (int jj = 0; jj < 8; ++jj) {
            const unsigned w01 = (jj & 1) ? dq[jj >> 1].z : dq[jj >> 1].x;
            const unsigned w23 = (jj & 1) ? dq[jj >> 1].w : dq[jj >> 1].y;
            const uint4 fvv = *(const uint4*)(fv8 + jj * 128);
            const uint4 v0 = *(const uint4*)(tabp + (w01 & 0xFFFFu));
            const uint4 v1 = *(const uint4*)(tabp + (w01 >> 16));
            const uint4 v2 = *(const uint4*)(tabp + (w23 & 0xFFFFu));
            const uint4 v3 = *(const uint4*)(tabp + (w23 >> 16));

            hacc[0][0] = __hfma2(u2h2(v0.x), u2h2(fvv.x), hacc[0][0]);
            hacc[0][1] = __hfma2(u2h2(v0.y), u2h2(fvv.y), hacc[0][1]);
            hacc[0][2] = __hfma2(u2h2(v0.z), u2h2(fvv.z), hacc[0][2]);
            hacc[0][3] = __hfma2(u2h2(v0.w), u2h2(fvv.w), hacc[0][3]);
            hacc[1][0] = __hfma2(u2h2(v1.x), u2h2(fvv.x), hacc[1][0]);
            hacc[1][1] = __hfma2(u2h2(v1.y), u2h2(fvv.y), hacc[1][1]);
            hacc[1][2] = __hfma2(u2h2(v1.z), u2h2(fvv.z), hacc[1][2]);
            hacc[1][3] = __hfma2(u2h2(v1.w), u2h2(fvv.w), hacc[1][3]);
            hacc[2][0] = __hfma2(u2h2(v2.x), u2h2(fvv.x), hacc[2][0]);
            hacc[2][1] = __hfma2(u2h2(v2.y), u2h2(fvv.y), hacc[2][1]);
            hacc[2][2] = __hfma2(u2h2(v2.z), u2h2(fvv.z), hacc[2][2]);
            hacc[2][3] = __hfma2(u2h2(v2.w), u2h2(fvv.w), hacc[2][3]);
            hacc[3][0] = __hfma2(u2h2(v3.x), u2h2(fvv.x), hacc[3][0]);
            hacc[3][1] = __hfma2(u2h2(v3.y), u2h2(fvv.y), hacc[3][1]);
            hacc[3][2] = __hfma2(u2h2(v3.z), u2h2(fvv.z), hacc[3][2]);
            hacc[3][3] = __hfma2(u2h2(v3.w), u2h2(fvv.w), hacc[3][3]);
        }

#pragma unroll
        for (int rr = 0; rr < 4; ++rr) {
            float2 q0 = __half22float2(hacc[rr][0]);
            float2 q1 = __half22float2(hacc[rr][1]);
            acc[rr][0].x += q0.x; acc[rr][0].y += q0.y;
            acc[rr][0].z += q1.x; acc[rr][0].w += q1.y;
            q0 = __half22float2(hacc[rr][2]);
            q1 = __half22float2(hacc[rr][3]);
            acc[rr][1].x += q0.x; acc[rr][1].y += q0.y;
            acc[rr][1].z += q1.x; acc[rr][1].w += q1.y;
        }
    }

    // E) 3-round log-tree reduction over the 8 jo octiles.
    //    Scratch layout [chunk][slot] (float4) -> conflict-free STS/LDS.
    float4* red4 = (float4*)fh;
    const int low5 = tid & 31;  // = rq*8 + fq, unique per (rq, fq)
    __syncthreads();  // all fv reads done before overwrite

#pragma unroll
    for (int round = 0; round < 3; ++round) {
        const int half = 4 >> round;  // 4, 2, 1
        if (jo >= half && jo < 2 * half) {
            const int slot = (jo - half) * 32 + low5;
#pragma unroll
            for (int rr = 0; rr < 4; ++rr) {
                red4[(rr * 2 + 0) * 128 + slot] = acc[rr][0];
                red4[(rr * 2 + 1) * 128 + slot] = acc[rr][1];
            }
        }
        __syncthreads();
        if (jo < half) {
            const int slot = jo * 32 + low5;
#pragma unroll
            for (int rr = 0; rr < 4; ++rr) {
#pragma unroll
                for (int hh = 0; hh < 2; ++hh) {
                    const float4 p = red4[(rr * 2 + hh) * 128 + slot];
                    acc[rr][hh].x += p.x; acc[rr][hh].y += p.y;
                    acc[rr][hh].z += p.z; acc[rr][hh].w += p.w;
                }
            }
        }
        __syncthreads();
    }

    if (jo == 0) {
        const int row0 = cta * 16 + rq * 4;
#pragma unroll
        for (int rr = 0; rr < 4; ++rr) {
            float4 o;
            o.x = softplus_acc(acc[rr][0].x); o.y = softplus_acc(acc[rr][0].y);
            o.z = softplus_acc(acc[rr][0].z); o.w = softplus_acc(acc[rr][0].w);
            *(float4*)(out + (row0 + rr) * Fn + fq * 4) = o;
            o.x = softplus_acc(acc[rr][1].x); o.y = softplus_acc(acc[rr][1].y);
            o.z = softplus_acc(acc[rr][1].z); o.w = softplus_acc(acc[rr][1].w);
            *(float4*)(out + (row0 + rr) * Fn + 32 + fq * 4) = o;
        }
    }
}

// ---------------------------------------------------------------------------
extern "C" void kernel_launch(void* const* d_in, const int* in_sizes, int n_in,
                              void* d_out, int out_size) {
    const float* r_batch = (const float*)d_in[0];  // [16,256,3]
    const float* f_batch = (const float*)d_in[1];  // [16,256,64]
    const float* w1 = (const float*)d_in[2];       // [128]
    const float* b1 = (const float*)d_in[3];       // [128]
    const float* W2 = (const float*)d_in[4];       // [128,64]
    const float* b2 = (const float*)d_in[5];       // [64]
    float* out = (float*)d_out;                    // [16,256,64]

    build_table_kernel<<<Tn, Hn>>>(w1, b1, W2, b2);

    const int smem_bytes = 106496 + 3072;  // 109568 B (~107 KB, 2 CTAs/SM)
    static bool attr_set = false;
    if (!attr_set) {
        cudaFuncSetAttribute(mp_main_kernel,
                             cudaFuncAttributeMaxDynamicSharedMemorySize,
                             smem_bytes);
        attr_set = true;
    }
    mp_main_kernel<<<(Bn * Nn) / 16, 256, smem_bytes>>>(r_batch, f_batch, out);
}